// round 4
// baseline (speedup 1.0000x reference)
#include <cuda_runtime.h>
#include <cuda_bf16.h>
#include <cstdint>

// Problem dims
#define B_  32
#define I_  128
#define O_  256
#define E_  8
#define HW_ 3136   // 56*56
#define HH_ 56
#define WW_ 56
#define HID_ 32
#define PER_EXPERT (O_*I_*9)   // 294912

// Scratch (allocation-free: __device__ globals)
__device__ float g_pool[B_*I_];
__device__ float g_r[B_*E_];
__device__ float g_cb[B_*O_];
__device__ float g_cw[(size_t)B_*O_*I_*9];   // 37.75 MB

// ---------------------------------------------------------------------------
// packed f32x2 helpers (Blackwell FFMA2 path)
// ---------------------------------------------------------------------------
__device__ __forceinline__ unsigned long long pk2(float lo, float hi) {
    unsigned long long r;
    asm("mov.b64 %0, {%1, %2};" : "=l"(r) : "f"(lo), "f"(hi));
    return r;
}
__device__ __forceinline__ unsigned long long fma2(unsigned long long a,
                                                   unsigned long long b,
                                                   unsigned long long c) {
    unsigned long long d;
    asm("fma.rn.f32x2 %0, %1, %2, %3;" : "=l"(d) : "l"(a), "l"(b), "l"(c));
    return d;
}
__device__ __forceinline__ void upk2(unsigned long long v, float& lo, float& hi) {
    asm("mov.b64 {%0, %1}, %2;" : "=f"(lo), "=f"(hi) : "l"(v));
}

// ---------------------------------------------------------------------------
// Kernel 0: global average pool, spread over 256 blocks for bandwidth.
// grid (8, 32): block = (channel-group cg, sample b); 8 warps x 2 channels.
// ---------------------------------------------------------------------------
__global__ __launch_bounds__(256) void pool_kernel(const float* __restrict__ x)
{
    int cg = blockIdx.x;            // 0..7
    int b  = blockIdx.y;            // 0..31
    int lane = threadIdx.x & 31, warp = threadIdx.x >> 5;

    #pragma unroll
    for (int r = 0; r < 2; r++) {
        int c = cg * 16 + warp * 2 + r;
        const float* xc = x + ((size_t)b * I_ + c) * HW_;
        float s = 0.f;
        for (int i = lane; i < HW_; i += 32) s += xc[i];
        #pragma unroll
        for (int o = 16; o; o >>= 1) s += __shfl_xor_sync(0xffffffffu, s, o);
        if (lane == 0) g_pool[b * I_ + c] = s * (1.0f / (float)HW_);
    }
}

// ---------------------------------------------------------------------------
// Kernel 1: routing MLP + softmax + combined bias. One block per sample.
// ---------------------------------------------------------------------------
__global__ __launch_bounds__(256) void mlp_kernel(
    const float* __restrict__ bias,
    const float* __restrict__ w1, const float* __restrict__ b1,
    const float* __restrict__ w2, const float* __restrict__ b2)
{
    int b = blockIdx.x;
    __shared__ float s_pool[I_];
    __shared__ float s_h[HID_];
    __shared__ float s_logit[E_];
    __shared__ float s_r[E_];

    int t = threadIdx.x;
    if (t < I_) s_pool[t] = g_pool[b * I_ + t];
    __syncthreads();

    if (t < HID_) {
        float s = b1[t];
        #pragma unroll 8
        for (int i = 0; i < I_; i++) s += s_pool[i] * w1[t * I_ + i];
        s_h[t] = fmaxf(s, 0.f);
    }
    __syncthreads();

    if (t < E_) {
        float s = b2[t];
        #pragma unroll
        for (int j = 0; j < HID_; j++) s += s_h[j] * w2[t * HID_ + j];
        s_logit[t] = s;
    }
    __syncthreads();

    if (t < E_) {
        float m = s_logit[0];
        #pragma unroll
        for (int e = 1; e < E_; e++) m = fmaxf(m, s_logit[e]);
        float den = 0.f;
        #pragma unroll
        for (int e = 0; e < E_; e++) den += expf(s_logit[e] - m);
        float rv = expf(s_logit[t] - m) / den;
        s_r[t] = rv;
        g_r[b * E_ + t] = rv;
    }
    __syncthreads();

    if (t < O_) {
        float s = 0.f;
        #pragma unroll
        for (int e = 0; e < E_; e++) s += s_r[e] * bias[e * O_ + t];
        g_cb[b * O_ + t] = s;
    }
}

// ---------------------------------------------------------------------------
// Kernel 2: combine per-sample weights, float4-vectorized.
// cw[b,*] = sum_e r[b,e] * W[e,*]
// ---------------------------------------------------------------------------
__global__ __launch_bounds__(256) void combine_kernel(const float* __restrict__ weight)
{
    size_t v = (size_t)blockIdx.x * 256 + threadIdx.x;   // float4 index
    int b = (int)(v / (PER_EXPERT / 4));
    size_t rest = v % (PER_EXPERT / 4);

    const float4* w4 = (const float4*)weight;
    float4 acc = make_float4(0.f, 0.f, 0.f, 0.f);
    #pragma unroll
    for (int e = 0; e < E_; e++) {
        float r = g_r[b * E_ + e];
        float4 wv = w4[(size_t)e * (PER_EXPERT / 4) + rest];
        acc.x = fmaf(r, wv.x, acc.x);
        acc.y = fmaf(r, wv.y, acc.y);
        acc.z = fmaf(r, wv.z, acc.z);
        acc.w = fmaf(r, wv.w, acc.w);
    }
    ((float4*)g_cw)[v] = acc;
}

// ---------------------------------------------------------------------------
// Kernel 3: direct 3x3 conv with per-sample weights, packed f32x2 FMA.
// Block: (sample b, 64 out-channels, 4 rows x 56 cols). 256 threads.
// Thread: 8 oc x 7 cols -> per oc: 3 packed pairs (cols 0-5) + 1 scalar (col 6).
// ---------------------------------------------------------------------------
#define ICC 8
#define XROWS 6
#define XCOLS 58

__global__ __launch_bounds__(256) void conv_kernel(
    const float* __restrict__ x, float* __restrict__ out)
{
    int b   = blockIdx.z;
    int oc0 = blockIdx.y * 64;
    int r0  = blockIdx.x * 4;

    __shared__ float  xs[ICC * XROWS * XCOLS];   // 11.1 KB
    __shared__ float2 ws2[64 * ICC * 9];         // 36.9 KB (weight duplicated {w,w})

    int t    = threadIdx.x;
    int ocg  = t >> 5;          // 0..7 (uniform in warp -> broadcast LDS.64 on w)
    int pix  = t & 31;
    int row  = pix >> 3;        // 0..3
    int col0 = (pix & 7) * 7;   // 0,7,...,49

    unsigned long long accp[8][3];
    float accs[8];
    #pragma unroll
    for (int j = 0; j < 8; j++) {
        accp[j][0] = accp[j][1] = accp[j][2] = 0ull;
        accs[j] = 0.f;
    }

    const float* xb  = x + (size_t)b * I_ * HW_;
    const float* cwb = g_cw + ((size_t)b * O_ + oc0) * (I_ * 9);

    for (int ic0 = 0; ic0 < I_; ic0 += ICC) {
        // stage x tile (halo + zero pad)
        for (int idx = t; idx < ICC * XROWS * XCOLS; idx += 256) {
            int ic  = idx / (XROWS * XCOLS);
            int rem = idx % (XROWS * XCOLS);
            int rr  = rem / XCOLS;
            int cc  = rem % XCOLS;
            int gh  = r0 - 1 + rr;
            int gw  = cc - 1;
            float v = 0.f;
            if (gh >= 0 && gh < HH_ && gw >= 0 && gw < WW_)
                v = xb[(size_t)(ic0 + ic) * HW_ + gh * WW_ + gw];
            xs[idx] = v;
        }
        // stage weight tile duplicated: ws2[oc][ic][k] = {w, w}
        for (int idx = t; idx < 64 * ICC * 9; idx += 256) {
            int oc  = idx / (ICC * 9);
            int rem = idx % (ICC * 9);
            int ic  = rem / 9;
            int k   = rem % 9;
            float w = cwb[(size_t)oc * (I_ * 9) + (ic0 + ic) * 9 + k];
            ws2[idx] = make_float2(w, w);
        }
        __syncthreads();

        #pragma unroll
        for (int ic = 0; ic < ICC; ic++) {
            #pragma unroll
            for (int kh = 0; kh < 3; kh++) {
                float xr[9];
                #pragma unroll
                for (int c = 0; c < 9; c++)
                    xr[c] = xs[ic * (XROWS * XCOLS) + (row + kh) * XCOLS + col0 + c];
                // packed x pairs (kw=2 reuses the even pairs of kw=0)
                unsigned long long p01 = pk2(xr[0], xr[1]);
                unsigned long long p23 = pk2(xr[2], xr[3]);
                unsigned long long p45 = pk2(xr[4], xr[5]);
                unsigned long long p12 = pk2(xr[1], xr[2]);
                unsigned long long p34 = pk2(xr[3], xr[4]);
                unsigned long long p56 = pk2(xr[5], xr[6]);
                unsigned long long p67 = pk2(xr[6], xr[7]);

                #pragma unroll
                for (int j = 0; j < 8; j++) {
                    const float2* wp = &ws2[(ocg * 8 + j) * (ICC * 9) + ic * 9 + kh * 3];
                    // kw = 0
                    {
                        float2 wv = wp[0];
                        unsigned long long w2 = pk2(wv.x, wv.y);
                        accp[j][0] = fma2(w2, p01, accp[j][0]);
                        accp[j][1] = fma2(w2, p23, accp[j][1]);
                        accp[j][2] = fma2(w2, p45, accp[j][2]);
                        accs[j]    = fmaf(wv.x, xr[6], accs[j]);
                    }
                    // kw = 1
                    {
                        float2 wv = wp[1];
                        unsigned long long w2 = pk2(wv.x, wv.y);
                        accp[j][0] = fma2(w2, p12, accp[j][0]);
                        accp[j][1] = fma2(w2, p34, accp[j][1]);
                        accp[j][2] = fma2(w2, p56, accp[j][2]);
                        accs[j]    = fmaf(wv.x, xr[7], accs[j]);
                    }
                    // kw = 2
                    {
                        float2 wv = wp[2];
                        unsigned long long w2 = pk2(wv.x, wv.y);
                        accp[j][0] = fma2(w2, p23, accp[j][0]);
                        accp[j][1] = fma2(w2, p45, accp[j][1]);
                        accp[j][2] = fma2(w2, p67, accp[j][2]);
                        accs[j]    = fmaf(wv.x, xr[8], accs[j]);
                    }
                }
            }
        }
        __syncthreads();
    }

    // epilogue: add per-sample bias, store
    int h = r0 + row;
    #pragma unroll
    for (int j = 0; j < 8; j++) {
        int oc = oc0 + ocg * 8 + j;
        float cb = g_cb[b * O_ + oc];
        float* op = out + ((size_t)b * O_ + oc) * HW_ + h * WW_ + col0;
        float lo, hi;
        upk2(accp[j][0], lo, hi); op[0] = lo + cb; op[1] = hi + cb;
        upk2(accp[j][1], lo, hi); op[2] = lo + cb; op[3] = hi + cb;
        upk2(accp[j][2], lo, hi); op[4] = lo + cb; op[5] = hi + cb;
        op[6] = accs[j] + cb;
    }
}

// ---------------------------------------------------------------------------
extern "C" void kernel_launch(void* const* d_in, const int* in_sizes, int n_in,
                              void* d_out, int out_size)
{
    const float* x      = (const float*)d_in[0];
    const float* weight = (const float*)d_in[1];
    const float* bias   = (const float*)d_in[2];
    const float* w1     = (const float*)d_in[3];
    const float* b1     = (const float*)d_in[4];
    const float* w2     = (const float*)d_in[5];
    const float* b2     = (const float*)d_in[6];
    float* out = (float*)d_out;

    dim3 pg(8, B_);
    pool_kernel<<<pg, 256>>>(x);
    mlp_kernel<<<B_, 256>>>(bias, w1, b1, w2, b2);

    size_t cw_vec = (size_t)B_ * PER_EXPERT / 4;          // float4 count
    combine_kernel<<<(unsigned)(cw_vec / 256), 256>>>(weight);

    dim3 grid(HH_ / 4, O_ / 64, B_);                      // (14, 4, 32)
    conv_kernel<<<grid, 256>>>(x, out);
}

// round 6
// speedup vs baseline: 3.5560x; 3.5560x over previous
#include <cuda_runtime.h>
#include <cuda_bf16.h>
#include <cstdint>

// Problem dims
#define B_  32
#define I_  128
#define O_  256
#define E_  8
#define HW_ 3136   // 56*56
#define HH_ 56
#define WW_ 56
#define HID_ 32
#define PER_EXPERT (O_*I_*9)   // 294912

// Scratch (allocation-free: __device__ globals)
__device__ float g_pool[B_*I_];
__device__ float g_r[B_*E_];
__device__ float g_cb[B_*O_];
__device__ float g_cw[(size_t)B_*O_*I_*9];   // 37.75 MB

// ---------------------------------------------------------------------------
// tf32 helpers
// ---------------------------------------------------------------------------
__device__ __forceinline__ unsigned f2tf(float f) {
    unsigned u;
    asm("cvt.rna.tf32.f32 %0, %1;" : "=r"(u) : "f"(f));
    return u;
}
__device__ __forceinline__ void mma_tf32(float c[4],
                                         unsigned a0, unsigned a1, unsigned a2, unsigned a3,
                                         unsigned b0, unsigned b1) {
    asm("mma.sync.aligned.m16n8k8.row.col.f32.tf32.tf32.f32 "
        "{%0,%1,%2,%3}, {%4,%5,%6,%7}, {%8,%9}, {%0,%1,%2,%3};"
        : "+f"(c[0]), "+f"(c[1]), "+f"(c[2]), "+f"(c[3])
        : "r"(a0), "r"(a1), "r"(a2), "r"(a3), "r"(b0), "r"(b1));
}

// ---------------------------------------------------------------------------
// Kernel 0: global average pool, spread over 256 blocks.
// ---------------------------------------------------------------------------
__global__ __launch_bounds__(256) void pool_kernel(const float* __restrict__ x)
{
    int cg = blockIdx.x;            // 0..7
    int b  = blockIdx.y;            // 0..31
    int lane = threadIdx.x & 31, warp = threadIdx.x >> 5;

    #pragma unroll
    for (int r = 0; r < 2; r++) {
        int c = cg * 16 + warp * 2 + r;
        const float* xc = x + ((size_t)b * I_ + c) * HW_;
        float s = 0.f;
        for (int i = lane; i < HW_; i += 32) s += xc[i];
        #pragma unroll
        for (int o = 16; o; o >>= 1) s += __shfl_xor_sync(0xffffffffu, s, o);
        if (lane == 0) g_pool[b * I_ + c] = s * (1.0f / (float)HW_);
    }
}

// ---------------------------------------------------------------------------
// Kernel 1: routing MLP + softmax + combined bias. One block per sample.
// ---------------------------------------------------------------------------
__global__ __launch_bounds__(256) void mlp_kernel(
    const float* __restrict__ bias,
    const float* __restrict__ w1, const float* __restrict__ b1,
    const float* __restrict__ w2, const float* __restrict__ b2)
{
    int b = blockIdx.x;
    __shared__ float s_pool[I_];
    __shared__ float s_h[HID_];
    __shared__ float s_logit[E_];
    __shared__ float s_r[E_];

    int t = threadIdx.x;
    if (t < I_) s_pool[t] = g_pool[b * I_ + t];
    __syncthreads();

    if (t < HID_) {
        float s = b1[t];
        #pragma unroll 8
        for (int i = 0; i < I_; i++) s += s_pool[i] * w1[t * I_ + i];
        s_h[t] = fmaxf(s, 0.f);
    }
    __syncthreads();

    if (t < E_) {
        float s = b2[t];
        #pragma unroll
        for (int j = 0; j < HID_; j++) s += s_h[j] * w2[t * HID_ + j];
        s_logit[t] = s;
    }
    __syncthreads();

    if (t < E_) {
        float m = s_logit[0];
        #pragma unroll
        for (int e = 1; e < E_; e++) m = fmaxf(m, s_logit[e]);
        float den = 0.f;
        #pragma unroll
        for (int e = 0; e < E_; e++) den += expf(s_logit[e] - m);
        float rv = expf(s_logit[t] - m) / den;
        s_r[t] = rv;
        g_r[b * E_ + t] = rv;
    }
    __syncthreads();

    if (t < O_) {
        float s = 0.f;
        #pragma unroll
        for (int e = 0; e < E_; e++) s += s_r[e] * bias[e * O_ + t];
        g_cb[b * O_ + t] = s;
    }
}

// ---------------------------------------------------------------------------
// Kernel 2: combine per-sample weights, float4-vectorized.
// ---------------------------------------------------------------------------
__global__ __launch_bounds__(256) void combine_kernel(const float* __restrict__ weight)
{
    size_t v = (size_t)blockIdx.x * 256 + threadIdx.x;   // float4 index
    int b = (int)(v / (PER_EXPERT / 4));
    size_t rest = v % (PER_EXPERT / 4);

    const float4* w4 = (const float4*)weight;
    float4 acc = make_float4(0.f, 0.f, 0.f, 0.f);
    #pragma unroll
    for (int e = 0; e < E_; e++) {
        float r = g_r[b * E_ + e];
        float4 wv = w4[(size_t)e * (PER_EXPERT / 4) + rest];
        acc.x = fmaf(r, wv.x, acc.x);
        acc.y = fmaf(r, wv.y, acc.y);
        acc.z = fmaf(r, wv.z, acc.z);
        acc.w = fmaf(r, wv.w, acc.w);
    }
    ((float4*)g_cw)[v] = acc;
}

// ---------------------------------------------------------------------------
// Kernel 3: tf32 tensor-core implicit-GEMM conv.
// Block: (sample b, 64 oc, 2 out rows x 56 cols = 112 px). 256 thr = 8 warps.
// Warp grid: 4 (M: 16 oc each) x 2 (N: one out row, 56 px = 7 n8-frags).
// K-loop: ic in steps of 8; inner: 9 (kh,kw) shifts, one m16n8k8 per n-frag.
//   A[m=oc][k=ic] = ws[oc][ic][kh*3+kw]   (per-sample combined weights, tf32)
//   B[k=ic][n=px] = xs[ic][warpN+kh][col+kw]  (x tile with halo, tf32)
// ---------------------------------------------------------------------------
#define ICC   8
#define XROWS 4
#define XCOLS 58
#define XSTRIDE (XROWS*XCOLS)      // 232
#define WSTRIDE 72                 // 8 ic * 9 k per oc

__global__ __launch_bounds__(256) void conv_kernel(
    const float* __restrict__ x, float* __restrict__ out)
{
    int b   = blockIdx.z;
    int oc0 = blockIdx.y * 64;
    int r0  = blockIdx.x * 2;       // 2 output rows per block

    __shared__ unsigned xs[ICC * XSTRIDE];    // 1856 * 4 = 7.4 KB  (tf32 bits)
    __shared__ unsigned ws[64 * WSTRIDE];     // 4608 * 4 = 18.4 KB (tf32 bits)

    int t     = threadIdx.x;
    int lane  = t & 31;
    int warp  = t >> 5;
    int warpM = warp >> 1;          // 0..3 -> oc rows [warpM*16, +16)
    int warpN = warp & 1;           // 0..1 -> out row r0+warpN
    int gid   = lane >> 2;          // 0..7
    int tig   = lane & 3;           // 0..3

    float acc[7][4];
    #pragma unroll
    for (int f = 0; f < 7; f++)
        #pragma unroll
        for (int q = 0; q < 4; q++) acc[f][q] = 0.f;

    const float* xb  = x + (size_t)b * I_ * HW_;
    const float* cwb = g_cw + ((size_t)b * O_ + oc0) * (I_ * 9);

    for (int ic0 = 0; ic0 < I_; ic0 += ICC) {
        // stage x tile: 8 ic x 4 rows (r0-1 .. r0+2, zero-padded) x 58 cols
        for (int idx = t; idx < ICC * XSTRIDE; idx += 256) {
            int ic  = idx / XSTRIDE;
            int rem = idx % XSTRIDE;
            int rr  = rem / XCOLS;
            int cc  = rem % XCOLS;
            int gh  = r0 - 1 + rr;
            int gw  = cc - 1;
            float v = 0.f;
            if (gh >= 0 && gh < HH_ && gw >= 0 && gw < WW_)
                v = xb[(size_t)(ic0 + ic) * HW_ + gh * WW_ + gw];
            xs[idx] = f2tf(v);
        }
        // stage weight tile: 64 oc x 8 ic x 9 k  (same layout as gmem slice)
        for (int idx = t; idx < 64 * WSTRIDE; idx += 256) {
            int oc  = idx / WSTRIDE;
            int rem = idx % WSTRIDE;
            int ic  = rem / 9;
            int kk  = rem % 9;
            ws[idx] = f2tf(cwb[(size_t)oc * (I_ * 9) + (ic0 + ic) * 9 + kk]);
        }
        __syncthreads();

        #pragma unroll
        for (int kh = 0; kh < 3; kh++) {
            int xrow = (warpN + kh) * XCOLS;
            #pragma unroll
            for (int kw = 0; kw < 3; kw++) {
                int kk = kh * 3 + kw;
                // A fragment (m16 x k8), row-major
                const unsigned* wbase = ws + (warpM * 16) * WSTRIDE + kk;
                unsigned a0 = wbase[(gid    ) * WSTRIDE +  tig      * 9];
                unsigned a1 = wbase[(gid + 8) * WSTRIDE +  tig      * 9];
                unsigned a2 = wbase[(gid    ) * WSTRIDE + (tig + 4) * 9];
                unsigned a3 = wbase[(gid + 8) * WSTRIDE + (tig + 4) * 9];

                #pragma unroll
                for (int f = 0; f < 7; f++) {
                    int cc = f * 8 + gid + kw;   // xs col for n = f*8+gid
                    unsigned b0 = xs[ tig      * XSTRIDE + xrow + cc];
                    unsigned b1 = xs[(tig + 4) * XSTRIDE + xrow + cc];
                    mma_tf32(acc[f], a0, a1, a2, a3, b0, b1);
                }
            }
        }
        __syncthreads();
    }

    // epilogue: add per-sample bias, store (float2 per fragment row)
    int h = r0 + warpN;
    int ocA = oc0 + warpM * 16 + gid;       // rows c0/c1
    int ocB = ocA + 8;                      // rows c2/c3
    float cbA = g_cb[b * O_ + ocA];
    float cbB = g_cb[b * O_ + ocB];
    float* outA = out + ((size_t)b * O_ + ocA) * HW_ + h * WW_;
    float* outB = out + ((size_t)b * O_ + ocB) * HW_ + h * WW_;
    #pragma unroll
    for (int f = 0; f < 7; f++) {
        int col = f * 8 + tig * 2;
        *(float2*)(outA + col) = make_float2(acc[f][0] + cbA, acc[f][1] + cbA);
        *(float2*)(outB + col) = make_float2(acc[f][2] + cbB, acc[f][3] + cbB);
    }
}

// ---------------------------------------------------------------------------
extern "C" void kernel_launch(void* const* d_in, const int* in_sizes, int n_in,
                              void* d_out, int out_size)
{
    const float* x      = (const float*)d_in[0];
    const float* weight = (const float*)d_in[1];
    const float* bias   = (const float*)d_in[2];
    const float* w1     = (const float*)d_in[3];
    const float* b1     = (const float*)d_in[4];
    const float* w2     = (const float*)d_in[5];
    const float* b2     = (const float*)d_in[6];
    float* out = (float*)d_out;

    dim3 pg(8, B_);
    pool_kernel<<<pg, 256>>>(x);
    mlp_kernel<<<B_, 256>>>(bias, w1, b1, w2, b2);

    size_t cw_vec = (size_t)B_ * PER_EXPERT / 4;          // float4 count
    combine_kernel<<<(unsigned)(cw_vec / 256), 256>>>(weight);

    dim3 grid(HH_ / 2, O_ / 64, B_);                      // (28, 4, 32)
    conv_kernel<<<grid, 256>>>(x, out);
}

// round 8
// speedup vs baseline: 6.3920x; 1.7975x over previous
#include <cuda_runtime.h>
#include <cuda_bf16.h>
#include <cstdint>

// Problem dims
#define B_  32
#define I_  128
#define O_  256
#define E_  8
#define HW_ 3136   // 56*56
#define HH_ 56
#define WW_ 56
#define HID_ 32
#define PER_EXPERT (O_*I_*9)   // 294912

// Scratch (allocation-free: __device__ globals)
__device__ float g_pool[B_*I_];
__device__ float g_r[B_*E_];
__device__ float g_cb[B_*O_];
__device__ float g_cw[(size_t)B_*O_*I_*9];   // 37.75 MB (tf32-rounded floats)

// ---------------------------------------------------------------------------
// tf32 helpers
// ---------------------------------------------------------------------------
__device__ __forceinline__ unsigned f2tf(float f) {
    unsigned u;
    asm("cvt.rna.tf32.f32 %0, %1;" : "=r"(u) : "f"(f));
    return u;
}
__device__ __forceinline__ void mma_tf32(float c[4],
                                         unsigned a0, unsigned a1, unsigned a2, unsigned a3,
                                         unsigned b0, unsigned b1) {
    asm("mma.sync.aligned.m16n8k8.row.col.f32.tf32.tf32.f32 "
        "{%0,%1,%2,%3}, {%4,%5,%6,%7}, {%8,%9}, {%0,%1,%2,%3};"
        : "+f"(c[0]), "+f"(c[1]), "+f"(c[2]), "+f"(c[3])
        : "r"(a0), "r"(a1), "r"(a2), "r"(a3), "r"(b0), "r"(b1));
}

// ---------------------------------------------------------------------------
// Kernel 0: global average pool, spread over 256 blocks.
// ---------------------------------------------------------------------------
__global__ __launch_bounds__(256) void pool_kernel(const float* __restrict__ x)
{
    int cg = blockIdx.x;            // 0..7
    int b  = blockIdx.y;            // 0..31
    int lane = threadIdx.x & 31, warp = threadIdx.x >> 5;

    #pragma unroll
    for (int r = 0; r < 2; r++) {
        int c = cg * 16 + warp * 2 + r;
        const float* xc = x + ((size_t)b * I_ + c) * HW_;
        float s = 0.f;
        for (int i = lane; i < HW_; i += 32) s += xc[i];
        #pragma unroll
        for (int o = 16; o; o >>= 1) s += __shfl_xor_sync(0xffffffffu, s, o);
        if (lane == 0) g_pool[b * I_ + c] = s * (1.0f / (float)HW_);
    }
}

// ---------------------------------------------------------------------------
// Kernel 1: routing MLP + softmax + combined bias. One block per sample.
// ---------------------------------------------------------------------------
__global__ __launch_bounds__(256) void mlp_kernel(
    const float* __restrict__ bias,
    const float* __restrict__ w1, const float* __restrict__ b1,
    const float* __restrict__ w2, const float* __restrict__ b2)
{
    int b = blockIdx.x;
    __shared__ float s_pool[I_];
    __shared__ float s_h[HID_];
    __shared__ float s_logit[E_];
    __shared__ float s_r[E_];

    int t = threadIdx.x;
    if (t < I_) s_pool[t] = g_pool[b * I_ + t];
    __syncthreads();

    if (t < HID_) {
        float s = b1[t];
        #pragma unroll 8
        for (int i = 0; i < I_; i++) s += s_pool[i] * w1[t * I_ + i];
        s_h[t] = fmaxf(s, 0.f);
    }
    __syncthreads();

    if (t < E_) {
        float s = b2[t];
        #pragma unroll
        for (int j = 0; j < HID_; j++) s += s_h[j] * w2[t * HID_ + j];
        s_logit[t] = s;
    }
    __syncthreads();

    if (t < E_) {
        float m = s_logit[0];
        #pragma unroll
        for (int e = 1; e < E_; e++) m = fmaxf(m, s_logit[e]);
        float den = 0.f;
        #pragma unroll
        for (int e = 0; e < E_; e++) den += expf(s_logit[e] - m);
        float rv = expf(s_logit[t] - m) / den;
        s_r[t] = rv;
        g_r[b * E_ + t] = rv;
    }
    __syncthreads();

    if (t < O_) {
        float s = 0.f;
        #pragma unroll
        for (int e = 0; e < E_; e++) s += s_r[e] * bias[e * O_ + t];
        g_cb[b * O_ + t] = s;
    }
}

// ---------------------------------------------------------------------------
// Kernel 2: combine per-sample weights, float4; outputs tf32-rounded floats.
// ---------------------------------------------------------------------------
__global__ __launch_bounds__(256) void combine_kernel(const float* __restrict__ weight)
{
    size_t v = (size_t)blockIdx.x * 256 + threadIdx.x;   // float4 index
    int b = (int)(v / (PER_EXPERT / 4));
    size_t rest = v % (PER_EXPERT / 4);

    const float4* w4 = (const float4*)weight;
    float4 acc = make_float4(0.f, 0.f, 0.f, 0.f);
    #pragma unroll
    for (int e = 0; e < E_; e++) {
        float r = g_r[b * E_ + e];
        float4 wv = w4[(size_t)e * (PER_EXPERT / 4) + rest];
        acc.x = fmaf(r, wv.x, acc.x);
        acc.y = fmaf(r, wv.y, acc.y);
        acc.z = fmaf(r, wv.z, acc.z);
        acc.w = fmaf(r, wv.w, acc.w);
    }
    // pre-round to tf32 so the conv staging is a pure bit copy
    acc.x = __uint_as_float(f2tf(acc.x));
    acc.y = __uint_as_float(f2tf(acc.y));
    acc.z = __uint_as_float(f2tf(acc.z));
    acc.w = __uint_as_float(f2tf(acc.w));
    ((float4*)g_cw)[v] = acc;
}

// ---------------------------------------------------------------------------
// Kernel 3: tf32 tensor-core implicit-GEMM conv, paired-k smem layouts.
// Block: (sample b, 64 oc, 4 out rows x 56 cols). 256 thr = 8 warps.
// Warp grid: 2 (M: 32 oc each) x 4 (N: one out row). Per warp: 2 m16 frags.
// K-loop: ic step 8 stored as uint2 pairs {ic0+tig, ic0+tig+4} so every
// MMA fragment load is a single conflict-free LDS.64.
// ---------------------------------------------------------------------------
#define XR_   6                  // rows r0-1 .. r0+4
#define XC_   58                 // cols with halo
#define XTSTRIDE 356             // uint2 per tig slice: 6*58=348 + 8 pad (banks)
#define XSLOT_N  1392            // 4 * 348 uint2 total
#define WOCSTRIDE 36             // uint2 per oc: 9 kk * 4 tig
#define WSLOT_N  2304            // 64 * 36

__global__ __launch_bounds__(256, 2) void conv_kernel(
    const float* __restrict__ x, float* __restrict__ out)
{
    int b   = blockIdx.z;
    int oc0 = blockIdx.y * 64;
    int r0  = blockIdx.x * 4;       // 4 output rows per block

    __shared__ uint2 xs2[4 * XTSTRIDE];        // 11.4 KB
    __shared__ uint2 ws2[WSLOT_N];             // 18.4 KB

    int t     = threadIdx.x;
    int lane  = t & 31;
    int warp  = t >> 5;
    int warpM = warp >> 2;          // 0..1 -> oc [warpM*32, +32)
    int warpN = warp & 3;           // 0..3 -> out row r0+warpN
    int gid   = lane >> 2;          // 0..7
    int tig   = lane & 3;           // 0..3

    // ---- precompute staging descriptors (once; no div/mod in the k-loop) ----
    int xg[6]; int xsof[6]; bool xv[6]; bool xin[6];
    #pragma unroll
    for (int i = 0; i < 6; i++) {
        int idx = t + 256 * i;
        bool in = (idx < XSLOT_N);
        int ii  = in ? idx : 0;
        int tg  = ii / 348;
        int rem = ii % 348;
        int rr  = rem / XC_;
        int cc  = rem % XC_;
        int gh  = r0 - 1 + rr;
        int gw  = cc - 1;
        bool v  = in && (gh >= 0) && (gh < HH_) && (gw >= 0) && (gw < WW_);
        xin[i]  = in;
        xv[i]   = v;
        xg[i]   = tg * HW_ + (v ? (gh * WW_ + gw) : 0);
        xsof[i] = tg * XTSTRIDE + rem;
    }
    int wg[9];
    #pragma unroll
    for (int i = 0; i < 9; i++) {
        int idx = t + 256 * i;          // == oc*36 + kk*4 + tig
        int oc  = idx / WOCSTRIDE;
        int r36 = idx % WOCSTRIDE;
        int kk  = r36 >> 2;
        int tg  = r36 & 3;
        wg[i]   = oc * (I_ * 9) + tg * 9 + kk;
    }

    float acc0[7][4], acc1[7][4];
    #pragma unroll
    for (int f = 0; f < 7; f++)
        #pragma unroll
        for (int q = 0; q < 4; q++) { acc0[f][q] = 0.f; acc1[f][q] = 0.f; }

    const float* xb  = x + (size_t)b * I_ * HW_;
    const float* cwb = g_cw + ((size_t)b * O_ + oc0) * (I_ * 9);

    const uint2* xbase  = xs2 + tig * XTSTRIDE + warpN * XC_ + gid;
    const uint2* wbase  = ws2 + (warpM * 32 + gid) * WOCSTRIDE + tig;

    for (int ic0 = 0; ic0 < I_; ic0 += 8) {
        // stage x pairs
        const float* xp = xb + (size_t)ic0 * HW_;
        #pragma unroll
        for (int i = 0; i < 6; i++) {
            if (xin[i]) {
                float v0 = xv[i] ? xp[xg[i]] : 0.f;
                float v1 = xv[i] ? xp[xg[i] + 4 * HW_] : 0.f;
                xs2[xsof[i]] = make_uint2(f2tf(v0), f2tf(v1));
            }
        }
        // stage weight pairs (already tf32-rounded; pure bit copy)
        const float* cwp = cwb + ic0 * 9;
        #pragma unroll
        for (int i = 0; i < 9; i++) {
            float w0 = cwp[wg[i]];
            float w1 = cwp[wg[i] + 36];
            ws2[t + 256 * i] = make_uint2(__float_as_uint(w0), __float_as_uint(w1));
        }
        __syncthreads();

        #pragma unroll
        for (int kh = 0; kh < 3; kh++) {
            #pragma unroll
            for (int kw = 0; kw < 3; kw++) {
                int kk = kh * 3 + kw;
                uint2 aA = wbase[kk * 4];
                uint2 aB = wbase[kk * 4 +  8 * WOCSTRIDE];
                uint2 aC = wbase[kk * 4 + 16 * WOCSTRIDE];
                uint2 aD = wbase[kk * 4 + 24 * WOCSTRIDE];
                const uint2* bp = xbase + kh * XC_ + kw;
                #pragma unroll
                for (int f = 0; f < 7; f++) {
                    uint2 bv = bp[f * 8];
                    mma_tf32(acc0[f], aA.x, aB.x, aA.y, aB.y, bv.x, bv.y);
                    mma_tf32(acc1[f], aC.x, aD.x, aC.y, aD.y, bv.x, bv.y);
                }
            }
        }
        __syncthreads();
    }

    // ---- epilogue: add per-sample bias, store ----
    int h = r0 + warpN;
    #pragma unroll
    for (int m = 0; m < 2; m++) {
        int ocA = oc0 + warpM * 32 + m * 16 + gid;
        int ocB = ocA + 8;
        float cbA = g_cb[b * O_ + ocA];
        float cbB = g_cb[b * O_ + ocB];
        float* outA = out + ((size_t)b * O_ + ocA) * HW_ + h * WW_;
        float* outB = out + ((size_t)b * O_ + ocB) * HW_ + h * WW_;
        float (*acc)[4] = m ? acc1 : acc0;
        #pragma unroll
        for (int f = 0; f < 7; f++) {
            int col = f * 8 + tig * 2;
            *(float2*)(outA + col) = make_float2(acc[f][0] + cbA, acc[f][1] + cbA);
            *(float2*)(outB + col) = make_float2(acc[f][2] + cbB, acc[f][3] + cbB);
        }
    }
}

// ---------------------------------------------------------------------------
extern "C" void kernel_launch(void* const* d_in, const int* in_sizes, int n_in,
                              void* d_out, int out_size)
{
    const float* x      = (const float*)d_in[0];
    const float* weight = (const float*)d_in[1];
    const float* bias   = (const float*)d_in[2];
    const float* w1     = (const float*)d_in[3];
    const float* b1     = (const float*)d_in[4];
    const float* w2     = (const float*)d_in[5];
    const float* b2     = (const float*)d_in[6];
    float* out = (float*)d_out;

    dim3 pg(8, B_);
    pool_kernel<<<pg, 256>>>(x);
    mlp_kernel<<<B_, 256>>>(bias, w1, b1, w2, b2);

    size_t cw_vec = (size_t)B_ * PER_EXPERT / 4;          // float4 count
    combine_kernel<<<(unsigned)(cw_vec / 256), 256>>>(weight);

    dim3 grid(HH_ / 4, O_ / 64, B_);                      // (14, 4, 32)
    conv_kernel<<<grid, 256>>>(x, out);
}

// round 11
// speedup vs baseline: 6.6786x; 1.0448x over previous
#include <cuda_runtime.h>
#include <cuda_bf16.h>
#include <cstdint>

// Problem dims
#define B_  32
#define I_  128
#define O_  256
#define E_  8
#define HW_ 3136   // 56*56
#define HH_ 56
#define WW_ 56
#define HID_ 32
#define PER_EXPERT (O_*I_*9)   // 294912

// Scratch (allocation-free: __device__ globals)
__device__ float g_pool[B_*I_];
__device__ float g_r[B_*E_];
__device__ float g_cb[B_*O_];
// x repacked: [b][s(16)][tig(4)][hw(3136)] uint2 = {tf32(ic=s*8+tig), tf32(ic+4)}
__device__ uint2 g_xp[(size_t)B_*16*4*HW_];            // 51.4 MB
// combined weights pre-swizzled: slab (b, ocg(4), s(16)) of [oc64][kk9][tig4] uint2
__device__ uint2 g_cw2[(size_t)B_*4*16*64*9*4];        // 37.75 MB

// ---------------------------------------------------------------------------
// helpers
// ---------------------------------------------------------------------------
__device__ __forceinline__ unsigned f2tf(float f) {
    unsigned u;
    asm("cvt.rna.tf32.f32 %0, %1;" : "=r"(u) : "f"(f));
    return u;
}
__device__ __forceinline__ void mma_tf32(float c[4],
                                         unsigned a0, unsigned a1, unsigned a2, unsigned a3,
                                         unsigned b0, unsigned b1) {
    asm("mma.sync.aligned.m16n8k8.row.col.f32.tf32.tf32.f32 "
        "{%0,%1,%2,%3}, {%4,%5,%6,%7}, {%8,%9}, {%0,%1,%2,%3};"
        : "+f"(c[0]), "+f"(c[1]), "+f"(c[2]), "+f"(c[3])
        : "r"(a0), "r"(a1), "r"(a2), "r"(a3), "r"(b0), "r"(b1));
}
__device__ __forceinline__ void cpa16(uint32_t dst, const void* src) {
    asm volatile("cp.async.cg.shared.global [%0], [%1], 16;" :: "r"(dst), "l"(src) : "memory");
}

// ---------------------------------------------------------------------------
// Kernel 0: repack x to paired-tf32 layout + fused global average pool.
// grid (64, 32): blockIdx.x = s*4+tig, blockIdx.y = b. 256 threads.
// ---------------------------------------------------------------------------
__global__ __launch_bounds__(256) void repack_kernel(const float* __restrict__ x)
{
    int st = blockIdx.x;            // s*4 + tig
    int b  = blockIdx.y;
    int s  = st >> 2;
    int tg = st & 3;
    int c0 = s * 8 + tg;
    int c1 = c0 + 4;
    int t  = threadIdx.x;

    const float4* p0 = (const float4*)(x + ((size_t)b * I_ + c0) * HW_);
    const float4* p1 = (const float4*)(x + ((size_t)b * I_ + c1) * HW_);
    uint4* op = (uint4*)(g_xp + ((size_t)(b * 16 + s) * 4 + tg) * HW_);

    float s0 = 0.f, s1 = 0.f;
    for (int j = t; j < HW_ / 4; j += 256) {
        float4 v0 = p0[j];
        float4 v1 = p1[j];
        s0 += v0.x + v0.y + v0.z + v0.w;
        s1 += v1.x + v1.y + v1.z + v1.w;
        op[j * 2]     = make_uint4(f2tf(v0.x), f2tf(v1.x), f2tf(v0.y), f2tf(v1.y));
        op[j * 2 + 1] = make_uint4(f2tf(v0.z), f2tf(v1.z), f2tf(v0.w), f2tf(v1.w));
    }
    // pool reduce (block owns both channels fully)
    __shared__ float red[16];
    int lane = t & 31, warp = t >> 5;
    #pragma unroll
    for (int o = 16; o; o >>= 1) {
        s0 += __shfl_xor_sync(0xffffffffu, s0, o);
        s1 += __shfl_xor_sync(0xffffffffu, s1, o);
    }
    if (lane == 0) { red[warp * 2] = s0; red[warp * 2 + 1] = s1; }
    __syncthreads();
    if (t == 0) {
        float a = 0.f, bsum = 0.f;
        #pragma unroll
        for (int w = 0; w < 8; w++) { a += red[w * 2]; bsum += red[w * 2 + 1]; }
        g_pool[b * I_ + c0] = a * (1.0f / (float)HW_);
        g_pool[b * I_ + c1] = bsum * (1.0f / (float)HW_);
    }
}

// ---------------------------------------------------------------------------
// Kernel 1: routing MLP + softmax + combined bias. One block per sample.
// ---------------------------------------------------------------------------
__global__ __launch_bounds__(256) void mlp_kernel(
    const float* __restrict__ bias,
    const float* __restrict__ w1, const float* __restrict__ b1,
    const float* __restrict__ w2, const float* __restrict__ b2)
{
    int b = blockIdx.x;
    __shared__ float s_pool[I_];
    __shared__ float s_h[HID_];
    __shared__ float s_logit[E_];
    __shared__ float s_r[E_];

    int t = threadIdx.x;
    if (t < I_) s_pool[t] = g_pool[b * I_ + t];
    __syncthreads();

    if (t < HID_) {
        float s = b1[t];
        #pragma unroll 8
        for (int i = 0; i < I_; i++) s += s_pool[i] * w1[t * I_ + i];
        s_h[t] = fmaxf(s, 0.f);
    }
    __syncthreads();

    if (t < E_) {
        float s = b2[t];
        #pragma unroll
        for (int j = 0; j < HID_; j++) s += s_h[j] * w2[t * HID_ + j];
        s_logit[t] = s;
    }
    __syncthreads();

    if (t < E_) {
        float m = s_logit[0];
        #pragma unroll
        for (int e = 1; e < E_; e++) m = fmaxf(m, s_logit[e]);
        float den = 0.f;
        #pragma unroll
        for (int e = 0; e < E_; e++) den += expf(s_logit[e] - m);
        float rv = expf(s_logit[t] - m) / den;
        s_r[t] = rv;
        g_r[b * E_ + t] = rv;
    }
    __syncthreads();

    if (t < O_) {
        float s = 0.f;
        #pragma unroll
        for (int e = 0; e < E_; e++) s += s_r[e] * bias[e * O_ + t];
        g_cb[b * O_ + t] = s;
    }
}

// ---------------------------------------------------------------------------
// Kernel 2: combine weights -> pre-swizzled paired-tf32 layout.
// One block per oc (256 blocks, 256 thr). Stage 8 expert rows (1152 floats
// each) in smem once, then emit all 32 samples' outputs.
// ---------------------------------------------------------------------------
__global__ __launch_bounds__(256) void combine_kernel(const float* __restrict__ weight)
{
    int oc  = blockIdx.x;           // 0..255
    int ocg = oc >> 6;
    int ocl = oc & 63;
    int t   = threadIdx.x;

    __shared__ float wsm[E_][I_ * 9];    // 8 x 1152 = 36.9 KB
    __shared__ float rs[B_ * E_];        // 256

    #pragma unroll
    for (int e = 0; e < E_; e++) {
        const float4* src = (const float4*)(weight + ((size_t)e * O_ + oc) * (I_ * 9));
        float4* dst = (float4*)wsm[e];
        for (int j = t; j < (I_ * 9) / 4; j += 256) dst[j] = src[j];
    }
    rs[t] = g_r[t];                      // 256 = 32*8
    __syncthreads();

    #pragma unroll
    for (int i = 0; i < 3; i++) {
        int slot = t + 256 * i;          // (s, kk, tg): 16*9*4 = 576 slots
        if (slot >= 576) break;
        int s   = slot / 36;
        int r36 = slot % 36;
        int kk  = r36 >> 2;
        int tg  = r36 & 3;
        int ic0 = s * 8 + tg;

        float wv0[E_], wv1[E_];
        #pragma unroll
        for (int e = 0; e < E_; e++) {
            wv0[e] = wsm[e][ic0 * 9 + kk];
            wv1[e] = wsm[e][(ic0 + 4) * 9 + kk];
        }
        for (int b = 0; b < B_; b++) {
            float a0 = 0.f, a1 = 0.f;
            #pragma unroll
            for (int e = 0; e < E_; e++) {
                float r = rs[b * E_ + e];
                a0 = fmaf(r, wv0[e], a0);
                a1 = fmaf(r, wv1[e], a1);
            }
            size_t idx = ((size_t)((b * 4 + ocg) * 16 + s) * 64 + ocl) * 36 + kk * 4 + tg;
            g_cw2[idx] = make_uint2(f2tf(a0), f2tf(a1));
        }
    }
}

// ---------------------------------------------------------------------------
// Kernel 3: tf32 implicit-GEMM conv. Fully async staging, double-buffered.
// Block: (b, 64 oc, 4 rows x 56 cols). 8 warps = 2 M x 4 N.
// smem (dynamic, 59904B): xs[2][1440] uint2, ws[2][2304] uint2.
// x slice stride 360 uint2 (row stride 60) -> bank index tig*8+gid: conflict-free.
// ---------------------------------------------------------------------------
#define XSLICE 360              // uint2 per tig slice (6 rows * 60)
#define XBUF   1440             // 4 slices
#define WBUF   2304             // 64*36
#define XSLAB_BYTES (4*HW_*8)   // per (b,s) x slab: 100352 B
#define WSLAB_BYTES (WBUF*8)    // 18432 B

__global__ __launch_bounds__(256, 2) void conv_kernel(float* __restrict__ out)
{
    extern __shared__ uint2 dsm[];
    uint2* xsb[2] = { dsm, dsm + XBUF };
    uint2* wsb[2] = { dsm + 2 * XBUF, dsm + 2 * XBUF + WBUF };
    uint32_t smem_u32 = (uint32_t)__cvta_generic_to_shared(dsm);

    int b   = blockIdx.z;
    int ocg = blockIdx.y;
    int oc0 = ocg * 64;
    int r0  = blockIdx.x * 4;

    int t     = threadIdx.x;
    int lane  = t & 31;
    int warp  = t >> 5;
    int warpM = warp >> 2;
    int warpN = warp & 3;
    int gid   = lane >> 2;
    int tig   = lane & 3;

    // ---- zero x buffers (halo rows/cols stay zero forever) ----
    for (int i = t; i < 2 * XBUF; i += 256) dsm[i] = make_uint2(0u, 0u);

    // ---- per-thread cp.async descriptors (step-invariant) ----
    // x: 672 16B chunks: (tig4) x (rr6) x (28 chunks of 2 uint2)
    uint32_t xdst[3]; uint32_t xsrc[3]; bool xval[3];
    #pragma unroll
    for (int i = 0; i < 3; i++) {
        int ch  = t + 256 * i;
        bool in = (ch < 672);
        int c   = in ? ch : 0;
        int tg  = c / 168;
        int rem = c % 168;
        int rr  = rem / 28;
        int c16 = rem % 28;
        int gh  = r0 - 1 + rr;
        xval[i] = in && (gh >= 0) && (gh < HH_);
        xsrc[i] = (uint32_t)((tg * HW_ + gh * WW_ + c16 * 2) * 8);
        xdst[i] = (uint32_t)((tg * XSLICE + rr * 60 + 2 + c16 * 2) * 8);
    }
    // w: 1152 16B chunks
    const char* xsrc_base = (const char*)(g_xp + (size_t)b * 16 * 4 * HW_);
    const char* wsrc_base = (const char*)(g_cw2 + (size_t)(b * 4 + ocg) * 16 * WBUF);

    __syncthreads();   // zeros visible before first cp.async

    // ---- prologue: stage step 0 into buffer 0 ----
    {
        const char* xp = xsrc_base;
        #pragma unroll
        for (int i = 0; i < 3; i++)
            if (xval[i]) cpa16(smem_u32 + xdst[i], xp + xsrc[i]);
        const char* wp = wsrc_base;
        uint32_t wdst0 = smem_u32 + 2 * XBUF * 8;
        #pragma unroll
        for (int i = 0; i < 5; i++) {
            int ch = t + 256 * i;
            if (ch < 1152) cpa16(wdst0 + ch * 16, wp + ch * 16);
        }
        asm volatile("cp.async.commit_group;" ::: "memory");
        asm volatile("cp.async.wait_group 0;" ::: "memory");
    }
    __syncthreads();

    float acc0[7][4], acc1[7][4];
    #pragma unroll
    for (int f = 0; f < 7; f++)
        #pragma unroll
        for (int q = 0; q < 4; q++) { acc0[f][q] = 0.f; acc1[f][q] = 0.f; }

    for (int s = 0; s < 16; s++) {
        int cur = s & 1, nxt = cur ^ 1;

        // prefetch step s+1 into the other buffer
        if (s < 15) {
            const char* xp = xsrc_base + (size_t)(s + 1) * XSLAB_BYTES;
            uint32_t xb_u = smem_u32 + nxt * XBUF * 8;
            #pragma unroll
            for (int i = 0; i < 3; i++)
                if (xval[i]) cpa16(xb_u + xdst[i], xp + xsrc[i]);
            const char* wp = wsrc_base + (size_t)(s + 1) * WSLAB_BYTES;
            uint32_t wb_u = smem_u32 + (2 * XBUF + nxt * WBUF) * 8;
            #pragma unroll
            for (int i = 0; i < 5; i++) {
                int ch = t + 256 * i;
                if (ch < 1152) cpa16(wb_u + ch * 16, wp + ch * 16);
            }
        }
        asm volatile("cp.async.commit_group;" ::: "memory");

        // MMA on current buffers
        const uint2* xbase = xsb[cur] + tig * XSLICE + warpN * 60 + gid + 1;
        const uint2* wbase = wsb[cur] + (warpM * 32 + gid) * 36 + tig;

        #pragma unroll
        for (int kh = 0; kh < 3; kh++) {
            #pragma unroll
            for (int kw = 0; kw < 3; kw++) {
                int kk = kh * 3 + kw;
                uint2 aA = wbase[kk * 4];
                uint2 aB = wbase[kk * 4 +  8 * 36];
                uint2 aC = wbase[kk * 4 + 16 * 36];
                uint2 aD = wbase[kk * 4 + 24 * 36];
                const uint2* bp = xbase + kh * 60 + kw;
                #pragma unroll
                for (int f = 0; f < 7; f++) {
                    uint2 bv = bp[f * 8];
                    mma_tf32(acc0[f], aA.x, aB.x, aA.y, aB.y, bv.x, bv.y);
                    mma_tf32(acc1[f], aC.x, aD.x, aC.y, aD.y, bv.x, bv.y);
                }
            }
        }

        asm volatile("cp.async.wait_group 0;" ::: "memory");
        __syncthreads();
    }

    // ---- epilogue ----
    int h = r0 + warpN;
    #pragma unroll
    for (int m = 0; m < 2; m++) {
        int ocA = oc0 + warpM * 32 + m * 16 + gid;
        int ocB = ocA + 8;
        float cbA = g_cb[b * O_ + ocA];
        float cbB = g_cb[b * O_ + ocB];
        float* outA = out + ((size_t)b * O_ + ocA) * HW_ + h * WW_;
        float* outB = out + ((size_t)b * O_ + ocB) * HW_ + h * WW_;
        float (*acc)[4] = m ? acc1 : acc0;
        #pragma unroll
        for (int f = 0; f < 7; f++) {
            int col = f * 8 + tig * 2;
            *(float2*)(outA + col) = make_float2(acc[f][0] + cbA, acc[f][1] + cbA);
            *(float2*)(outB + col) = make_float2(acc[f][2] + cbB, acc[f][3] + cbB);
        }
    }
}

// ---------------------------------------------------------------------------
extern "C" void kernel_launch(void* const* d_in, const int* in_sizes, int n_in,
                              void* d_out, int out_size)
{
    const float* x      = (const float*)d_in[0];
    const float* weight = (const float*)d_in[1];
    const float* bias   = (const float*)d_in[2];
    const float* w1     = (const float*)d_in[3];
    const float* b1     = (const float*)d_in[4];
    const float* w2     = (const float*)d_in[5];
    const float* b2     = (const float*)d_in[6];
    float* out = (float*)d_out;

    repack_kernel<<<dim3(64, B_), 256>>>(x);
    mlp_kernel<<<B_, 256>>>(bias, w1, b1, w2, b2);
    combine_kernel<<<O_, 256>>>(weight);

    int smem_bytes = (2 * XBUF + 2 * WBUF) * 8;   // 59904
    cudaFuncSetAttribute(conv_kernel, cudaFuncAttributeMaxDynamicSharedMemorySize, smem_bytes);
    dim3 grid(HH_ / 4, O_ / 64, B_);              // (14, 4, 32)
    conv_kernel<<<grid, 256, smem_bytes>>>(out);
}

// round 14
// speedup vs baseline: 11.5448x; 1.7286x over previous
#include <cuda_runtime.h>
#include <cuda_fp16.h>
#include <cstdint>

// Problem dims
#define B_  32
#define I_  128
#define O_  256
#define E_  8
#define HW_ 3136   // 56*56
#define HH_ 56
#define WW_ 56
#define HID_ 32
#define PER_EXPERT (O_*I_*9)   // 294912

// Scratch (allocation-free: __device__ globals)
__device__ float g_pool[B_*I_];
__device__ float g_r[B_*E_];
__device__ float g_cb[B_*O_];
// x packed fp16: [b][s(8)][tig(4)][hw] uint2 = {h2(ic,ic+1), h2(ic+8,ic+9)}, ic=16s+2tig
__device__ uint2 g_xp[(size_t)B_*8*4*HW_];             // 25.7 MB
// weights packed fp16: [b][ocg(4)][s(8)][oc64][kk9][tig4] uint2 (same pairing)
__device__ uint2 g_cw2[(size_t)B_*4*8*64*9*4];         // 18.9 MB

// ---------------------------------------------------------------------------
// helpers
// ---------------------------------------------------------------------------
__device__ __forceinline__ unsigned h2u(__half2 h) { return *(unsigned*)&h; }
__device__ __forceinline__ void mma_f16(float c[4],
                                        unsigned a0, unsigned a1, unsigned a2, unsigned a3,
                                        unsigned b0, unsigned b1) {
    asm("mma.sync.aligned.m16n8k16.row.col.f32.f16.f16.f32 "
        "{%0,%1,%2,%3}, {%4,%5,%6,%7}, {%8,%9}, {%0,%1,%2,%3};"
        : "+f"(c[0]), "+f"(c[1]), "+f"(c[2]), "+f"(c[3])
        : "r"(a0), "r"(a1), "r"(a2), "r"(a3), "r"(b0), "r"(b1));
}
__device__ __forceinline__ void cpa16(uint32_t dst, const void* src) {
    asm volatile("cp.async.cg.shared.global [%0], [%1], 16;" :: "r"(dst), "l"(src) : "memory");
}

// ---------------------------------------------------------------------------
// Kernel 0a: global average pool.
// ---------------------------------------------------------------------------
__global__ __launch_bounds__(256) void pool_kernel(const float* __restrict__ x)
{
    int cg = blockIdx.x, b = blockIdx.y;
    int lane = threadIdx.x & 31, warp = threadIdx.x >> 5;
    #pragma unroll
    for (int r = 0; r < 2; r++) {
        int c = cg * 16 + warp * 2 + r;
        const float* xc = x + ((size_t)b * I_ + c) * HW_;
        float s = 0.f;
        for (int i = lane; i < HW_; i += 32) s += xc[i];
        #pragma unroll
        for (int o = 16; o; o >>= 1) s += __shfl_xor_sync(0xffffffffu, s, o);
        if (lane == 0) g_pool[b * I_ + c] = s * (1.0f / (float)HW_);
    }
}

// ---------------------------------------------------------------------------
// Kernel 0b: repack x -> paired fp16 layout.
// grid (32, B): blockIdx.x = s*4+tig. Channels c0,c0+1,c0+8,c0+9 with c0=16s+2tig.
// ---------------------------------------------------------------------------
__global__ __launch_bounds__(256) void repack_kernel(const float* __restrict__ x)
{
    int st = blockIdx.x;
    int b  = blockIdx.y;
    int s  = st >> 2;
    int tg = st & 3;
    int c0 = s * 16 + tg * 2;
    int t  = threadIdx.x;

    const float2* p0 = (const float2*)(x + ((size_t)b * I_ + c0    ) * HW_);
    const float2* p1 = (const float2*)(x + ((size_t)b * I_ + c0 + 1) * HW_);
    const float2* p8 = (const float2*)(x + ((size_t)b * I_ + c0 + 8) * HW_);
    const float2* p9 = (const float2*)(x + ((size_t)b * I_ + c0 + 9) * HW_);
    uint4* op = (uint4*)(g_xp + ((size_t)(b * 8 + s) * 4 + tg) * HW_);

    for (int j = t; j < HW_ / 2; j += 256) {
        float2 v0 = p0[j], v1 = p1[j], v8 = p8[j], v9 = p9[j];
        op[j] = make_uint4(
            h2u(__floats2half2_rn(v0.x, v1.x)), h2u(__floats2half2_rn(v8.x, v9.x)),
            h2u(__floats2half2_rn(v0.y, v1.y)), h2u(__floats2half2_rn(v8.y, v9.y)));
    }
}

// ---------------------------------------------------------------------------
// Kernel 1: routing MLP + softmax + combined bias. One block per sample.
// ---------------------------------------------------------------------------
__global__ __launch_bounds__(256) void mlp_kernel(
    const float* __restrict__ bias,
    const float* __restrict__ w1, const float* __restrict__ b1,
    const float* __restrict__ w2, const float* __restrict__ b2)
{
    int b = blockIdx.x;
    __shared__ float s_pool[I_];
    __shared__ float s_h[HID_];
    __shared__ float s_logit[E_];
    __shared__ float s_r[E_];

    int t = threadIdx.x;
    if (t < I_) s_pool[t] = g_pool[b * I_ + t];
    __syncthreads();

    if (t < HID_) {
        float s = b1[t];
        #pragma unroll 8
        for (int i = 0; i < I_; i++) s += s_pool[i] * w1[t * I_ + i];
        s_h[t] = fmaxf(s, 0.f);
    }
    __syncthreads();

    if (t < E_) {
        float s = b2[t];
        #pragma unroll
        for (int j = 0; j < HID_; j++) s += s_h[j] * w2[t * HID_ + j];
        s_logit[t] = s;
    }
    __syncthreads();

    if (t < E_) {
        float m = s_logit[0];
        #pragma unroll
        for (int e = 1; e < E_; e++) m = fmaxf(m, s_logit[e]);
        float den = 0.f;
        #pragma unroll
        for (int e = 0; e < E_; e++) den += expf(s_logit[e] - m);
        float rv = expf(s_logit[t] - m) / den;
        s_r[t] = rv;
        g_r[b * E_ + t] = rv;
    }
    __syncthreads();

    if (t < O_) {
        float s = 0.f;
        #pragma unroll
        for (int e = 0; e < E_; e++) s += s_r[e] * bias[e * O_ + t];
        g_cb[b * O_ + t] = s;
    }
}

// ---------------------------------------------------------------------------
// Kernel 2: combine weights -> pre-swizzled paired-fp16 layout.
// One block per oc. Stage 8 expert rows in smem, emit all 32 samples.
// ---------------------------------------------------------------------------
__global__ __launch_bounds__(256) void combine_kernel(const float* __restrict__ weight)
{
    int oc  = blockIdx.x;           // 0..255
    int ocg = oc >> 6;
    int ocl = oc & 63;
    int t   = threadIdx.x;

    __shared__ float wsm[E_][I_ * 9];    // 36.9 KB
    __shared__ float rs[B_ * E_];

    #pragma unroll
    for (int e = 0; e < E_; e++) {
        const float4* src = (const float4*)(weight + ((size_t)e * O_ + oc) * (I_ * 9));
        float4* dst = (float4*)wsm[e];
        for (int j = t; j < (I_ * 9) / 4; j += 256) dst[j] = src[j];
    }
    rs[t] = g_r[t];
    __syncthreads();

    #pragma unroll
    for (int i = 0; i < 2; i++) {
        int slot = t + 256 * i;          // (s8, kk9, tg4): 288 slots
        if (slot >= 288) break;
        int s   = slot / 36;
        int r36 = slot % 36;
        int kk  = r36 >> 2;
        int tg  = r36 & 3;
        int ic  = s * 16 + tg * 2;

        float w0[E_], w1v[E_], w8[E_], w9[E_];
        #pragma unroll
        for (int e = 0; e < E_; e++) {
            w0[e]  = wsm[e][ ic      * 9 + kk];
            w1v[e] = wsm[e][(ic + 1) * 9 + kk];
            w8[e]  = wsm[e][(ic + 8) * 9 + kk];
            w9[e]  = wsm[e][(ic + 9) * 9 + kk];
        }
        for (int b = 0; b < B_; b++) {
            float a0 = 0.f, a1 = 0.f, a8 = 0.f, a9 = 0.f;
            #pragma unroll
            for (int e = 0; e < E_; e++) {
                float r = rs[b * E_ + e];
                a0 = fmaf(r, w0[e],  a0);
                a1 = fmaf(r, w1v[e], a1);
                a8 = fmaf(r, w8[e],  a8);
                a9 = fmaf(r, w9[e],  a9);
            }
            size_t idx = ((((size_t)(b * 4 + ocg) * 8 + s) * 64 + ocl) * 9 + kk) * 4 + tg;
            g_cw2[idx] = make_uint2(h2u(__floats2half2_rn(a0, a1)),
                                    h2u(__floats2half2_rn(a8, a9)));
        }
    }
}

// ---------------------------------------------------------------------------
// Kernel 3: fp16 m16n8k16 implicit-GEMM conv, async double-buffered.
// Block: (b, 64 oc, 4 rows x 56 cols). 8 warps = 2 M x 4 N. 8 K-steps of 16 ic.
// x slice stride 372 uint2 (≡4 mod 16) -> LDS.64 conflict-free.
// ---------------------------------------------------------------------------
#define XSLICE 372              // uint2 per tig slice (6 rows * 60, padded)
#define XBUF   1488             // 4 slices
#define WBUF   2304             // 64*36
#define XSLAB_BYTES (4*HW_*8)   // per (b,s) x slab: 100352 B
#define WSLAB_BYTES (WBUF*8)    // 18432 B

__global__ __launch_bounds__(256, 2) void conv_kernel(float* __restrict__ out)
{
    extern __shared__ uint2 dsm[];
    uint2* xsb[2] = { dsm, dsm + XBUF };
    uint2* wsb[2] = { dsm + 2 * XBUF, dsm + 2 * XBUF + WBUF };
    uint32_t smem_u32 = (uint32_t)__cvta_generic_to_shared(dsm);

    int b   = blockIdx.z;
    int ocg = blockIdx.y;
    int oc0 = ocg * 64;
    int r0  = blockIdx.x * 4;

    int t     = threadIdx.x;
    int lane  = t & 31;
    int warp  = t >> 5;
    int warpM = warp >> 2;
    int warpN = warp & 3;
    int gid   = lane >> 2;
    int tig   = lane & 3;

    // ---- zero x buffers (halo stays zero) ----
    for (int i = t; i < 2 * XBUF; i += 256) dsm[i] = make_uint2(0u, 0u);

    // ---- per-thread cp.async descriptors (step-invariant) ----
    uint32_t xdst[3]; uint32_t xsrc[3]; bool xval[3];
    #pragma unroll
    for (int i = 0; i < 3; i++) {
        int ch  = t + 256 * i;
        bool in = (ch < 672);
        int c   = in ? ch : 0;
        int tg  = c / 168;
        int rem = c % 168;
        int rr  = rem / 28;
        int c16 = rem % 28;
        int gh  = r0 - 1 + rr;
        xval[i] = in && (gh >= 0) && (gh < HH_);
        xsrc[i] = (uint32_t)((tg * HW_ + gh * WW_ + c16 * 2) * 8);
        xdst[i] = (uint32_t)((tg * XSLICE + rr * 60 + 2 + c16 * 2) * 8);
    }
    const char* xsrc_base = (const char*)(g_xp + (size_t)b * 8 * 4 * HW_);
    const char* wsrc_base = (const char*)(g_cw2 + (size_t)(b * 4 + ocg) * 8 * WBUF);

    __syncthreads();

    // ---- prologue: stage step 0 into buffer 0 ----
    {
        #pragma unroll
        for (int i = 0; i < 3; i++)
            if (xval[i]) cpa16(smem_u32 + xdst[i], xsrc_base + xsrc[i]);
        uint32_t wdst0 = smem_u32 + 2 * XBUF * 8;
        #pragma unroll
        for (int i = 0; i < 5; i++) {
            int ch = t + 256 * i;
            if (ch < 1152) cpa16(wdst0 + ch * 16, wsrc_base + ch * 16);
        }
        asm volatile("cp.async.commit_group;" ::: "memory");
        asm volatile("cp.async.wait_group 0;" ::: "memory");
    }
    __syncthreads();

    float acc0[7][4], acc1[7][4];
    #pragma unroll
    for (int f = 0; f < 7; f++)
        #pragma unroll
        for (int q = 0; q < 4; q++) { acc0[f][q] = 0.f; acc1[f][q] = 0.f; }

    for (int s = 0; s < 8; s++) {
        int cur = s & 1, nxt = cur ^ 1;

        if (s < 7) {
            const char* xp = xsrc_base + (size_t)(s + 1) * XSLAB_BYTES;
            uint32_t xb_u = smem_u32 + nxt * XBUF * 8;
            #pragma unroll
            for (int i = 0; i < 3; i++)
                if (xval[i]) cpa16(xb_u + xdst[i], xp + xsrc[i]);
            const char* wp = wsrc_base + (size_t)(s + 1) * WSLAB_BYTES;
            uint32_t wb_u = smem_u32 + (2 * XBUF + nxt * WBUF) * 8;
            #pragma unroll
            for (int i = 0; i < 5; i++) {
                int ch = t + 256 * i;
                if (ch < 1152) cpa16(wb_u + ch * 16, wp + ch * 16);
            }
        }
        asm volatile("cp.async.commit_group;" ::: "memory");

        const uint2* xbase = xsb[cur] + tig * XSLICE + warpN * 60 + gid + 1;
        const uint2* wbase = wsb[cur] + (warpM * 32 + gid) * 36 + tig;

        #pragma unroll
        for (int kh = 0; kh < 3; kh++) {
            #pragma unroll
            for (int kw = 0; kw < 3; kw++) {
                int kk = kh * 3 + kw;
                uint2 aA = wbase[kk * 4];
                uint2 aB = wbase[kk * 4 +  8 * 36];
                uint2 aC = wbase[kk * 4 + 16 * 36];
                uint2 aD = wbase[kk * 4 + 24 * 36];
                const uint2* bp = xbase + kh * 60 + kw;
                #pragma unroll
                for (int f = 0; f < 7; f++) {
                    uint2 bv = bp[f * 8];
                    mma_f16(acc0[f], aA.x, aB.x, aA.y, aB.y, bv.x, bv.y);
                    mma_f16(acc1[f], aC.x, aD.x, aC.y, aD.y, bv.x, bv.y);
                }
            }
        }

        asm volatile("cp.async.wait_group 0;" ::: "memory");
        __syncthreads();
    }

    // ---- epilogue ----
    int h = r0 + warpN;
    #pragma unroll
    for (int m = 0; m < 2; m++) {
        int ocA = oc0 + warpM * 32 + m * 16 + gid;
        int ocB = ocA + 8;
        float cbA = g_cb[b * O_ + ocA];
        float cbB = g_cb[b * O_ + ocB];
        float* outA = out + ((size_t)b * O_ + ocA) * HW_ + h * WW_;
        float* outB = out + ((size_t)b * O_ + ocB) * HW_ + h * WW_;
        float (*acc)[4] = m ? acc1 : acc0;
        #pragma unroll
        for (int f = 0; f < 7; f++) {
            int col = f * 8 + tig * 2;
            *(float2*)(outA + col) = make_float2(acc[f][0] + cbA, acc[f][1] + cbA);
            *(float2*)(outB + col) = make_float2(acc[f][2] + cbB, acc[f][3] + cbB);
        }
    }
}

// ---------------------------------------------------------------------------
extern "C" void kernel_launch(void* const* d_in, const int* in_sizes, int n_in,
                              void* d_out, int out_size)
{
    const float* x      = (const float*)d_in[0];
    const float* weight = (const float*)d_in[1];
    const float* bias   = (const float*)d_in[2];
    const float* w1     = (const float*)d_in[3];
    const float* b1     = (const float*)d_in[4];
    const float* w2     = (const float*)d_in[5];
    const float* b2     = (const float*)d_in[6];
    float* out = (float*)d_out;

    pool_kernel<<<dim3(8, B_), 256>>>(x);
    repack_kernel<<<dim3(32, B_), 256>>>(x);
    mlp_kernel<<<B_, 256>>>(bias, w1, b1, w2, b2);
    combine_kernel<<<O_, 256>>>(weight);

    int smem_bytes = (2 * XBUF + 2 * WBUF) * 8;   // 60672
    cudaFuncSetAttribute(conv_kernel, cudaFuncAttributeMaxDynamicSharedMemorySize, smem_bytes);
    dim3 grid(HH_ / 4, O_ / 64, B_);              // (14, 4, 32)
    conv_kernel<<<grid, 256, smem_bytes>>>(out);
}